// round 3
// baseline (speedup 1.0000x reference)
#include <cuda_runtime.h>
#include <cuda_bf16.h>
#include <math.h>

// Problem constants
#define U_CNT 512
#define P_CNT 1024
#define D_DIM 128
#define H_DIM 256
#define E_CNT 98304
#define N_NODES 1536
#define CSR_CAP (E_CNT + N_NODES)

#define GBLK 256          // persistent grid blocks (<= 2 per SM guaranteed)
#define NTHR 256

typedef unsigned long long u64;

// ---------------- packed f32x2 helpers (sm_100+) ------------------------------
__device__ __forceinline__ u64 pack2(float lo, float hi) {
    u64 r; asm("mov.b64 %0,{%1,%2};" : "=l"(r) : "f"(lo), "f"(hi)); return r;
}
__device__ __forceinline__ void unpack2(u64 v, float& lo, float& hi) {
    asm("mov.b64 {%0,%1},%2;" : "=f"(lo), "=f"(hi) : "l"(v));
}
__device__ __forceinline__ u64 add2(u64 a, u64 b) {
    u64 r; asm("add.rn.f32x2 %0,%1,%2;" : "=l"(r) : "l"(a), "l"(b)); return r;
}
__device__ __forceinline__ void fma2(u64& d, u64 a, u64 b) {
    asm("fma.rn.f32x2 %0,%1,%2,%0;" : "+l"(d) : "l"(a), "l"(b));
}
__device__ __forceinline__ u64 abs2(u64 a) {
    u64 r; asm("and.b64 %0,%1,0x7FFFFFFF7FFFFFFF;" : "=l"(r) : "l"(a)); return r;
}

// ---------------- scratch (device globals; no allocation allowed) -------------
__device__ float g_xA[N_NODES * H_DIM];
__device__ float g_xB[N_NODES * H_DIM];
__device__ float g_h [N_NODES * H_DIM];
__device__ int   g_deg[N_NODES];          // zero-init; scan resets each call
__device__ float g_dis[N_NODES];
__device__ int   g_ptr[N_NODES + 1];
__device__ int   g_cnt[N_NODES];          // zero-init; scan resets each call
__device__ int   g_src[CSR_CAP];
__device__ float g_uf[U_CNT * D_DIM];
__device__ float g_pf[P_CNT * D_DIM];
__device__ float g_Au[U_CNT * H_DIM];
__device__ float g_Bp[P_CNT * H_DIM];

// ---------------- software grid barrier ---------------------------------------
__device__ unsigned g_arrive;    // zero-init; returns to 0 after every barrier
__device__ unsigned g_gen;       // monotonically increasing generation

__device__ __forceinline__ void gsync() {
    __syncthreads();
    __threadfence();                                // release (also orders atomics)
    if (threadIdx.x == 0) {
        unsigned gen = atomicAdd(&g_gen, 0u);       // read BEFORE arriving
        unsigned old = atomicAdd(&g_arrive, 1u);
        if (old == GBLK - 1) {
            atomicExch(&g_arrive, 0u);
            __threadfence();
            atomicAdd(&g_gen, 1u);
        } else {
            while (atomicAdd(&g_gen, 0u) == gen) __nanosleep(64);
        }
    }
    __syncthreads();
    __threadfence();                                // acquire: invalidate L1D
}

// ---------------- shared memory union ------------------------------------------
struct AggS  { int src[256]; float w[256]; float red[128]; };
struct GemmS { float Xs[16][65]; float Ws[16][64]; };
struct PredS { float As[64][34]; float Bs[32][34]; u64 wh[16]; };
union SmemU { AggS a; GemmS g; PredS p; };

// ---------------- fp32 GEMM tile core (packed FFMA2) ---------------------------
// C[bm:+64, bn:+64] = X[.,K] @ W[K,N] (+bias, +relu)
__device__ __forceinline__ void gemm_core(
    GemmS& s, const float* __restrict__ X, const float* __restrict__ W,
    const float* __restrict__ bias, float* __restrict__ C,
    int N, int K, int bm, int bn, int relu)
{
    int tid = threadIdx.x;
    int tx = tid & 15, ty = tid >> 4;
    u64 acc[4][2] = {};
    for (int k0 = 0; k0 < K; k0 += 16) {
        {   // X tile: 64 rows x 16 k, transposed
            int kk = tid & 15, r = tid >> 4;
            #pragma unroll
            for (int rr = 0; rr < 4; rr++)
                s.Xs[kk][r + rr * 16] = X[(bm + r + rr * 16) * K + k0 + kk];
        }
        {   // W tile: 16 k x 64 cols
            int c = tid & 63, kr = tid >> 6;
            #pragma unroll
            for (int rr = 0; rr < 4; rr++)
                s.Ws[kr + rr * 4][c] = W[(k0 + kr + rr * 4) * N + bn + c];
        }
        __syncthreads();
        #pragma unroll
        for (int k = 0; k < 16; k++) {
            float4 rb = *(const float4*)&s.Ws[k][tx * 4];
            u64 rb01 = pack2(rb.x, rb.y), rb23 = pack2(rb.z, rb.w);
            #pragma unroll
            for (int i = 0; i < 4; i++) {
                float a = s.Xs[k][ty * 4 + i];
                u64 a2 = pack2(a, a);
                fma2(acc[i][0], a2, rb01);
                fma2(acc[i][1], a2, rb23);
            }
        }
        __syncthreads();
    }
    #pragma unroll
    for (int i = 0; i < 4; i++) {
        int row = bm + ty * 4 + i;
        #pragma unroll
        for (int jp = 0; jp < 2; jp++) {
            float lo, hi; unpack2(acc[i][jp], lo, hi);
            int col = bn + tx * 4 + jp * 2;
            if (bias) { lo += bias[col]; hi += bias[col + 1]; }
            if (relu) { lo = fmaxf(lo, 0.f); hi = fmaxf(hi, 0.f); }
            float2 o = make_float2(lo, hi);
            *(float2*)&C[row * N + col] = o;
        }
    }
}

// ---------------- aggregation bodies -------------------------------------------
// F=256: one thread per feature, 2 independent accumulators for MLP
__device__ __forceinline__ void agg256_body(
    AggS& s, const float* __restrict__ h, float* __restrict__ out, int dst)
{
    int f = threadIdx.x;
    float dd = g_dis[dst];
    int s0 = g_ptr[dst], s1 = g_ptr[dst + 1];
    float a0 = 0.f, a1 = 0.f;
    for (int base = s0; base < s1; base += 256) {
        int n = min(256, s1 - base);
        if (f < n) { int sc = g_src[base + f]; s.src[f] = sc; s.w[f] = g_dis[sc]; }
        __syncthreads();
        int i = 0;
        #pragma unroll 2
        for (; i + 1 < n; i += 2) {
            float v0 = h[s.src[i]     * 256 + f];
            float v1 = h[s.src[i + 1] * 256 + f];
            a0 += v0 * s.w[i];
            a1 += v1 * s.w[i + 1];
        }
        if (i < n) a0 += h[s.src[i] * 256 + f] * s.w[i];
        __syncthreads();
    }
    out[dst * 256 + f] = (a0 + a1) * dd;
}

// F=128: two threads per feature, each handles half the neighbor list
__device__ __forceinline__ void agg128_body(
    AggS& s, const float* __restrict__ h, float* __restrict__ out, int dst)
{
    int tid = threadIdx.x;
    int f = tid & 127, half = tid >> 7;
    float dd = g_dis[dst];
    int s0 = g_ptr[dst], s1 = g_ptr[dst + 1];
    float a0 = 0.f, a1 = 0.f;
    for (int base = s0; base < s1; base += 256) {
        int n = min(256, s1 - base);
        if (tid < n) { int sc = g_src[base + tid]; s.src[tid] = sc; s.w[tid] = g_dis[sc]; }
        __syncthreads();
        int i = half;
        for (; i + 2 < n; i += 4) {
            float v0 = h[s.src[i]     * 128 + f];
            float v1 = h[s.src[i + 2] * 128 + f];
            a0 += v0 * s.w[i];
            a1 += v1 * s.w[i + 2];
        }
        for (; i < n; i += 2) a0 += h[s.src[i] * 128 + f] * s.w[i];
        __syncthreads();
    }
    if (half) s.red[f] = a0 + a1;
    __syncthreads();
    if (!half) out[dst * 128 + f] = (a0 + a1 + s.red[f]) * dd;
    __syncthreads();
}

// ---------------- the persistent mega kernel -----------------------------------
__global__ void __launch_bounds__(NTHR, 2) mega_kernel(
    const int* __restrict__ uid, const int* __restrict__ pid,
    const int* __restrict__ edge,
    const float* __restrict__ ue, const float* __restrict__ pe,
    const float* __restrict__ W0, const float* __restrict__ b0,
    const float* __restrict__ W1, const float* __restrict__ b1,
    const float* __restrict__ W2, const float* __restrict__ b2,
    const float* __restrict__ Wu, const float* __restrict__ bu,
    const float* __restrict__ Wp, const float* __restrict__ bp,
    const float* __restrict__ Wq1, const float* __restrict__ bq1,
    const float* __restrict__ Wq2, const float* __restrict__ bq2,
    float* __restrict__ out)
{
    __shared__ __align__(16) SmemU sm;
    int bx = blockIdx.x, tid = threadIdx.x;
    int gt = bx * NTHR + tid, gs = GBLK * NTHR;

    // ---- P0: x0 gather + degree count -------------------------------------
    for (int idx = gt; idx < N_NODES * D_DIM; idx += gs) {
        int i = idx >> 7, d = idx & 127;
        float v;
        if (i < U_CNT) v = ue[uid[i] * D_DIM + d];
        else           v = pe[pid[i - U_CNT] * D_DIM + d];
        g_xA[idx] = v;
    }
    for (int e = gt; e < E_CNT; e += gs)
        atomicAdd(&g_deg[edge[E_CNT + e]], 1);
    gsync();

    // ---- P1: single-warp scan (block 0): deg+1, rsqrt, excl scan, reset ----
    if (bx == 0 && tid < 32) {
        const int PER = N_NODES / 32;       // 48
        int base = tid * PER;
        int v[PER]; int ssum = 0;
        #pragma unroll
        for (int i = 0; i < PER; i++) v[i] = g_deg[base + i] + 1;
        #pragma unroll
        for (int i = 0; i < PER; i++) {
            g_dis[base + i] = rsqrtf((float)v[i]);
            ssum += v[i];
            g_deg[base + i] = 0;
            g_cnt[base + i] = 0;
        }
        int incl = ssum;
        #pragma unroll
        for (int off = 1; off < 32; off <<= 1) {
            int u = __shfl_up_sync(0xffffffffu, incl, off);
            if (tid >= off) incl += u;
        }
        int run = incl - ssum;
        if (tid == 0) g_ptr[0] = 0;
        #pragma unroll
        for (int i = 0; i < PER; i++) { run += v[i]; g_ptr[base + i + 1] = run; }
    }
    gsync();

    // ---- P2: CSR fill ------------------------------------------------------
    for (int idx = gt; idx < E_CNT + N_NODES; idx += gs) {
        int s, d;
        if (idx < E_CNT) { s = edge[idx]; d = edge[E_CNT + idx]; }
        else             { s = d = idx - E_CNT; }
        int pos = g_ptr[d] + atomicAdd(&g_cnt[d], 1);
        g_src[pos] = s;
    }
    gsync();

    // ---- P3: agg<128> xA -> xB ---------------------------------------------
    for (int dst = bx; dst < N_NODES; dst += GBLK) agg128_body(sm.a, g_xA, g_xB, dst);
    gsync();

    // ---- P4: gemm xB[.,128] @ W0 -> xA[.,256] (relu) -----------------------
    for (int t = bx; t < 24 * 4; t += GBLK)
        gemm_core(sm.g, g_xB, W0, b0, g_xA, H_DIM, D_DIM, (t >> 2) * 64, (t & 3) * 64, 1);
    gsync();

    // ---- P5: agg<256> xA -> h ----------------------------------------------
    for (int dst = bx; dst < N_NODES; dst += GBLK) agg256_body(sm.a, g_xA, g_h, dst);
    gsync();

    // ---- P6: gemm h @ W1 -> xB (relu) --------------------------------------
    for (int t = bx; t < 24 * 4; t += GBLK)
        gemm_core(sm.g, g_h, W1, b1, g_xB, H_DIM, H_DIM, (t >> 2) * 64, (t & 3) * 64, 1);
    gsync();

    // ---- P7: agg<256> xB -> h ----------------------------------------------
    for (int dst = bx; dst < N_NODES; dst += GBLK) agg256_body(sm.a, g_xB, g_h, dst);
    gsync();

    // ---- P8: gemm h @ W2 -> xA (relu) --------------------------------------
    for (int t = bx; t < 24 * 4; t += GBLK)
        gemm_core(sm.g, g_h, W2, b2, g_xA, H_DIM, H_DIM, (t >> 2) * 64, (t & 3) * 64, 1);
    gsync();

    // ---- P9: dual projection: uf = xA_u @ Wu + bu ; pf = xA_p @ Wp + bp ----
    // tiles: 24 m-tiles (8 user, 16 paper) x 2 n-tiles
    for (int t = bx; t < 24 * 2; t += GBLK) {
        int mt = t >> 1, nt = t & 1;
        if (mt < 8)
            gemm_core(sm.g, g_xA, Wu, bu, g_uf, D_DIM, H_DIM, mt * 64, nt * 64, 0);
        else
            gemm_core(sm.g, g_xA + U_CNT * H_DIM, Wp, bp, g_pf, D_DIM, H_DIM,
                      (mt - 8) * 64, nt * 64, 0);
    }
    gsync();

    // ---- P10: dual predictor input: Au = uf @ Wq1a + bq1 ; Bp = pf @ Wq1b --
    for (int t = bx; t < 24 * 4; t += GBLK) {
        int mt = t >> 2, nt = t & 3;
        if (mt < 8)
            gemm_core(sm.g, g_uf, Wq1, bq1, g_Au, H_DIM, D_DIM, mt * 64, nt * 64, 0);
        else
            gemm_core(sm.g, g_pf, Wq1 + D_DIM * H_DIM, nullptr, g_Bp, H_DIM, D_DIM,
                      (mt - 8) * 64, nt * 64, 0);
    }
    gsync();

    // ---- P11: pairwise predictor, 64(u) x 32(p) tiles = 256 = GBLK ---------
    {
        int ut = bx >> 5, pt = bx & 31;        // 8 u-tiles x 32 p-tiles
        int u0 = ut * 64, p0 = pt * 32;
        int tx = tid & 15, ty = tid >> 4;
        u64 acc[4][2] = {};
        for (int j0 = 0; j0 < H_DIM; j0 += 32) {
            int c = tid & 31, r = tid >> 5;
            #pragma unroll
            for (int rr = 0; rr < 8; rr++)
                sm.p.As[r + rr * 8][c] = g_Au[(u0 + r + rr * 8) * H_DIM + j0 + c];
            #pragma unroll
            for (int rr = 0; rr < 4; rr++)
                sm.p.Bs[r + rr * 8][c] = g_Bp[(p0 + r + rr * 8) * H_DIM + j0 + c];
            if (tid < 16)
                sm.p.wh[tid] = pack2(0.5f * Wq2[j0 + 2 * tid], 0.5f * Wq2[j0 + 2 * tid + 1]);
            __syncthreads();
            #pragma unroll
            for (int jp = 0; jp < 16; jp++) {
                u64 wv = sm.p.wh[jp];
                u64 av[4], bv[2];
                #pragma unroll
                for (int i = 0; i < 4; i++)  av[i] = *(const u64*)&sm.p.As[ty + 16 * i][2 * jp];
                #pragma unroll
                for (int jj = 0; jj < 2; jj++) bv[jj] = *(const u64*)&sm.p.Bs[tx + 16 * jj][2 * jp];
                #pragma unroll
                for (int i = 0; i < 4; i++)
                    #pragma unroll
                    for (int jj = 0; jj < 2; jj++) {
                        u64 s = add2(av[i], bv[jj]);
                        u64 a = abs2(s);
                        fma2(acc[i][jj], wv, s);
                        fma2(acc[i][jj], wv, a);
                    }
            }
            __syncthreads();
        }
        float bb = bq2[0];
        #pragma unroll
        for (int i = 0; i < 4; i++) {
            int u = u0 + ty + 16 * i;
            #pragma unroll
            for (int jj = 0; jj < 2; jj++) {
                int p = p0 + tx + 16 * jj;
                float lo, hi; unpack2(acc[i][jj], lo, hi);
                float z = lo + hi + bb;
                out[u * P_CNT + p] = 1.f / (1.f + __expf(-z));
            }
        }
    }
}

// ---------------- driver --------------------------------------------------------
extern "C" void kernel_launch(void* const* d_in, const int* in_sizes, int n_in,
                              void* d_out, int out_size) {
    const int*   uid  = (const int*)  d_in[0];
    const int*   pid  = (const int*)  d_in[1];
    const int*   edge = (const int*)  d_in[2];
    // d_in[3] = user_paper_interactions (unused by the reference math)
    const float* ue   = (const float*)d_in[4];
    const float* pe   = (const float*)d_in[5];
    const float* W0   = (const float*)d_in[6];  const float* b0 = (const float*)d_in[7];
    const float* W1   = (const float*)d_in[8];  const float* b1 = (const float*)d_in[9];
    const float* W2   = (const float*)d_in[10]; const float* b2 = (const float*)d_in[11];
    const float* Wu   = (const float*)d_in[12]; const float* bu = (const float*)d_in[13];
    const float* Wp   = (const float*)d_in[14]; const float* bp = (const float*)d_in[15];
    const float* Wq1  = (const float*)d_in[16]; const float* bq1= (const float*)d_in[17];
    const float* Wq2  = (const float*)d_in[18]; const float* bq2= (const float*)d_in[19];
    float* out = (float*)d_out;

    mega_kernel<<<GBLK, NTHR>>>(uid, pid, edge, ue, pe,
                                W0, b0, W1, b1, W2, b2,
                                Wu, bu, Wp, bp, Wq1, bq1, Wq2, bq2, out);
}

// round 4
// speedup vs baseline: 1.2025x; 1.2025x over previous
#include <cuda_runtime.h>
#include <cuda_bf16.h>
#include <math.h>

// Problem constants
#define U_CNT 512
#define P_CNT 1024
#define D_DIM 128
#define H_DIM 256
#define E_CNT 98304
#define N_NODES 1536
#define CSR_CAP (E_CNT + N_NODES)

typedef unsigned long long u64;

// ---------------- packed f32x2 helpers (sm_100+) ------------------------------
__device__ __forceinline__ u64 pack2(float lo, float hi) {
    u64 r; asm("mov.b64 %0,{%1,%2};" : "=l"(r) : "f"(lo), "f"(hi)); return r;
}
__device__ __forceinline__ void unpack2(u64 v, float& lo, float& hi) {
    asm("mov.b64 {%0,%1},%2;" : "=f"(lo), "=f"(hi) : "l"(v));
}
__device__ __forceinline__ u64 add2(u64 a, u64 b) {
    u64 r; asm("add.rn.f32x2 %0,%1,%2;" : "=l"(r) : "l"(a), "l"(b)); return r;
}
__device__ __forceinline__ void fma2(u64& d, u64 a, u64 b) {
    asm("fma.rn.f32x2 %0,%1,%2,%0;" : "+l"(d) : "l"(a), "l"(b));
}
__device__ __forceinline__ u64 abs2(u64 a) {
    u64 r; asm("and.b64 %0,%1,0x7FFFFFFF7FFFFFFF;" : "=l"(r) : "l"(a)); return r;
}

// ---------------- scratch (device globals; no allocation allowed) -------------
__device__ float g_xA[N_NODES * H_DIM];
__device__ float g_xB[N_NODES * H_DIM];
__device__ float g_h [N_NODES * H_DIM];
__device__ int   g_deg[N_NODES];          // zero-init; scan resets each call
__device__ float g_dis[N_NODES];
__device__ int   g_ptr[N_NODES + 1];
__device__ int   g_cnt[N_NODES];          // zero-init; scan resets each call
__device__ int   g_src[CSR_CAP];
__device__ float g_C1[H_DIM * H_DIM];     // Wu @ Wq1[:128]
__device__ float g_C2[H_DIM * H_DIM];     // Wp @ Wq1[128:]
__device__ float g_bias1[H_DIM];
__device__ float g_bias2[H_DIM];
__device__ float g_AB[N_NODES * H_DIM];   // rows 0..511 = Au, 512..1535 = Bp

// ---------------- shared structs -----------------------------------------------
struct GemmS { float Xs[16][33]; float Ws[16][64]; };
struct AggS  { int src[256]; float w[256]; float red[128]; };

// ---------------- fp32 GEMM tile core: 32(M) x 64(N), packed FFMA2 -------------
__device__ __forceinline__ void gemm32_core(
    GemmS& s, const float* __restrict__ X, const float* __restrict__ W,
    const float* __restrict__ bias, float* __restrict__ C,
    int N, int K, int bm, int bn, int relu)
{
    int tid = threadIdx.x;
    int tx = tid & 15, ty = tid >> 4;
    u64 acc[2][2] = {};
    for (int k0 = 0; k0 < K; k0 += 16) {
        {   // X tile: 32 rows x 16 k, transposed into Xs[k][row]
            int kk = tid & 15, r = tid >> 4;
            s.Xs[kk][r]      = X[(bm + r) * K + k0 + kk];
            s.Xs[kk][r + 16] = X[(bm + r + 16) * K + k0 + kk];
        }
        {   // W tile: 16 k x 64 cols
            int c = tid & 63, kr = tid >> 6;
            #pragma unroll
            for (int rr = 0; rr < 4; rr++)
                s.Ws[kr + rr * 4][c] = W[(k0 + kr + rr * 4) * N + bn + c];
        }
        __syncthreads();
        #pragma unroll
        for (int k = 0; k < 16; k++) {
            float4 rb = *(const float4*)&s.Ws[k][tx * 4];
            u64 rb01 = pack2(rb.x, rb.y), rb23 = pack2(rb.z, rb.w);
            #pragma unroll
            for (int i = 0; i < 2; i++) {
                float a = s.Xs[k][ty * 2 + i];
                u64 a2 = pack2(a, a);
                fma2(acc[i][0], a2, rb01);
                fma2(acc[i][1], a2, rb23);
            }
        }
        __syncthreads();
    }
    #pragma unroll
    for (int i = 0; i < 2; i++) {
        int row = bm + ty * 2 + i;
        #pragma unroll
        for (int jp = 0; jp < 2; jp++) {
            float lo, hi; unpack2(acc[i][jp], lo, hi);
            int col = bn + tx * 4 + jp * 2;
            if (bias) { lo += bias[col]; hi += bias[col + 1]; }
            if (relu) { lo = fmaxf(lo, 0.f); hi = fmaxf(hi, 0.f); }
            float2 o = make_float2(lo, hi);
            *(float2*)&C[row * N + col] = o;
        }
    }
}

// ---------------- P1: x0 gather + degree count + weight-product prep -----------
// grid: 768 gather blocks + 64 prep-gemm blocks + 2 bias blocks = 834
__global__ void prep_kernel(const int* __restrict__ uid, const int* __restrict__ pid,
                            const float* __restrict__ ue, const float* __restrict__ pe,
                            const int* __restrict__ edge,
                            const float* __restrict__ Wu, const float* __restrict__ bu,
                            const float* __restrict__ Wp, const float* __restrict__ bp,
                            const float* __restrict__ Wq1, const float* __restrict__ bq1) {
    __shared__ __align__(16) GemmS sm;
    int bx = blockIdx.x, tid = threadIdx.x;
    if (bx < 768) {
        int idx = bx * 256 + tid;               // covers exactly 1536*128
        int i = idx >> 7, d = idx & 127;
        float v;
        if (i < U_CNT) v = ue[uid[i] * D_DIM + d];
        else           v = pe[pid[i - U_CNT] * D_DIM + d];
        g_xA[idx] = v;
        if (idx < E_CNT) atomicAdd(&g_deg[edge[E_CNT + idx]], 1);
    } else if (bx < 832) {
        int t = bx - 768;                       // 64 blocks: 32 per product
        int which = t >> 5, tt = t & 31;        // mt(8) x nt(4)
        int bm = (tt >> 2) * 32, bn = (tt & 3) * 64;
        if (which == 0)
            gemm32_core(sm, Wu, Wq1, nullptr, g_C1, H_DIM, D_DIM, bm, bn, 0);
        else
            gemm32_core(sm, Wp, Wq1 + D_DIM * H_DIM, nullptr, g_C2, H_DIM, D_DIM, bm, bn, 0);
    } else if (bx == 832) {
        float acc = bq1[tid];
        for (int d = 0; d < D_DIM; d++) acc += bu[d] * Wq1[d * H_DIM + tid];
        g_bias1[tid] = acc;
    } else {
        float acc = 0.f;
        for (int d = 0; d < D_DIM; d++) acc += bp[d] * Wq1[(D_DIM + d) * H_DIM + tid];
        g_bias2[tid] = acc;
    }
}

// ---------------- P2: single-warp scan -----------------------------------------
__global__ void scan_kernel() {
    int lane = threadIdx.x;                 // 32 threads
    const int PER = N_NODES / 32;           // 48
    int base = lane * PER;
    int v[PER]; int s = 0;
    #pragma unroll
    for (int i = 0; i < PER; i++) v[i] = g_deg[base + i] + 1;
    #pragma unroll
    for (int i = 0; i < PER; i++) {
        g_dis[base + i] = rsqrtf((float)v[i]);
        s += v[i];
        g_deg[base + i] = 0;
        g_cnt[base + i] = 0;
    }
    int incl = s;
    #pragma unroll
    for (int off = 1; off < 32; off <<= 1) {
        int u = __shfl_up_sync(0xffffffffu, incl, off);
        if (lane >= off) incl += u;
    }
    int run = incl - s;
    if (lane == 0) g_ptr[0] = 0;
    #pragma unroll
    for (int i = 0; i < PER; i++) { run += v[i]; g_ptr[base + i + 1] = run; }
}

// ---------------- P3: CSR fill --------------------------------------------------
__global__ void fill_kernel(const int* __restrict__ edge) {
    int idx = blockIdx.x * blockDim.x + threadIdx.x;
    if (idx >= E_CNT + N_NODES) return;
    int s, d;
    if (idx < E_CNT) { s = edge[idx]; d = edge[E_CNT + idx]; }
    else             { s = d = idx - E_CNT; }                  // self loop
    int pos = g_ptr[d] + atomicAdd(&g_cnt[d], 1);
    g_src[pos] = s;
}

// ---------------- aggregation kernels -------------------------------------------
// F=128: 256 threads, two threads per feature (each half of neighbor list)
__global__ void agg128_kernel(const float* __restrict__ h, float* __restrict__ out) {
    __shared__ AggS s;
    int tid = threadIdx.x, dst = blockIdx.x;
    int f = tid & 127, half = tid >> 7;
    float dd = g_dis[dst];
    int s0 = g_ptr[dst], s1 = g_ptr[dst + 1];
    float a0 = 0.f, a1 = 0.f;
    for (int base = s0; base < s1; base += 256) {
        int n = min(256, s1 - base);
        if (tid < n) { int sc = g_src[base + tid]; s.src[tid] = sc; s.w[tid] = g_dis[sc]; }
        __syncthreads();
        int i = half;
        for (; i + 2 < n; i += 4) {
            float v0 = h[s.src[i]     * 128 + f];
            float v1 = h[s.src[i + 2] * 128 + f];
            a0 += v0 * s.w[i];
            a1 += v1 * s.w[i + 2];
        }
        for (; i < n; i += 2) a0 += h[s.src[i] * 128 + f] * s.w[i];
        __syncthreads();
    }
    if (half) s.red[f] = a0 + a1;
    __syncthreads();
    if (!half) out[dst * 128 + f] = (a0 + a1 + s.red[f]) * dd;
}

// F=256: 256 threads, one per feature, 2 independent accumulators
__global__ void agg256_kernel(const float* __restrict__ h, float* __restrict__ out) {
    __shared__ AggS s;
    int f = threadIdx.x, dst = blockIdx.x;
    float dd = g_dis[dst];
    int s0 = g_ptr[dst], s1 = g_ptr[dst + 1];
    float a0 = 0.f, a1 = 0.f;
    for (int base = s0; base < s1; base += 256) {
        int n = min(256, s1 - base);
        { int sc; if (f < n) { sc = g_src[base + f]; s.src[f] = sc; s.w[f] = g_dis[sc]; } }
        __syncthreads();
        int i = 0;
        #pragma unroll 2
        for (; i + 1 < n; i += 2) {
            float v0 = h[s.src[i]     * 256 + f];
            float v1 = h[s.src[i + 1] * 256 + f];
            a0 += v0 * s.w[i];
            a1 += v1 * s.w[i + 1];
        }
        if (i < n) a0 += h[s.src[i] * 256 + f] * s.w[i];
        __syncthreads();
    }
    out[dst * 256 + f] = (a0 + a1) * dd;
}

// ---------------- layer GEMM (M=32 tiles) ---------------------------------------
__global__ void gemm_kernel(const float* __restrict__ X, const float* __restrict__ W,
                            const float* __restrict__ bias, float* __restrict__ C,
                            int K, int relu) {
    __shared__ __align__(16) GemmS sm;
    gemm32_core(sm, X, W, bias, C, H_DIM, K, blockIdx.y * 32, blockIdx.x * 64, relu);
}

// fused projector: AB[r] = xA[r] @ (r<512 ? C1 : C2) + bias{1,2}
__global__ void gemm_ab_kernel(const float* __restrict__ X) {
    __shared__ __align__(16) GemmS sm;
    int bm = blockIdx.y * 32, bn = blockIdx.x * 64;
    if (bm < U_CNT)
        gemm32_core(sm, X, g_C1, g_bias1, g_AB, H_DIM, H_DIM, bm, bn, 0);
    else
        gemm32_core(sm, X, g_C2, g_bias2, g_AB, H_DIM, H_DIM, bm, bn, 0);
}

// ---------------- pairwise predictor: 64(u) x 32(p) tiles -----------------------
__global__ void pred_kernel(const float* __restrict__ w2, const float* __restrict__ bq2,
                            float* __restrict__ out) {
    __shared__ __align__(16) float As[64][34];
    __shared__ __align__(16) float Bs[32][34];
    __shared__ u64 wh[16];
    const float* A = g_AB;                       // rows 0..511
    const float* B = g_AB + U_CNT * H_DIM;       // rows 512..1535
    int tid = threadIdx.x;
    int tx = tid & 15, ty = tid >> 4;
    int u0 = blockIdx.y * 64, p0 = blockIdx.x * 32;
    u64 acc[4][2] = {};
    for (int j0 = 0; j0 < H_DIM; j0 += 32) {
        int c = tid & 31, r = tid >> 5;
        #pragma unroll
        for (int rr = 0; rr < 8; rr++)
            As[r + rr * 8][c] = A[(u0 + r + rr * 8) * H_DIM + j0 + c];
        #pragma unroll
        for (int rr = 0; rr < 4; rr++)
            Bs[r + rr * 8][c] = B[(p0 + r + rr * 8) * H_DIM + j0 + c];
        if (tid < 16)
            wh[tid] = pack2(0.5f * w2[j0 + 2 * tid], 0.5f * w2[j0 + 2 * tid + 1]);
        __syncthreads();
        #pragma unroll
        for (int jp = 0; jp < 16; jp++) {
            u64 wv = wh[jp];
            u64 av[4], bv[2];
            #pragma unroll
            for (int i = 0; i < 4; i++)  av[i] = *(const u64*)&As[ty + 16 * i][2 * jp];
            #pragma unroll
            for (int jj = 0; jj < 2; jj++) bv[jj] = *(const u64*)&Bs[tx + 16 * jj][2 * jp];
            #pragma unroll
            for (int i = 0; i < 4; i++)
                #pragma unroll
                for (int jj = 0; jj < 2; jj++) {
                    u64 s = add2(av[i], bv[jj]);
                    u64 a = abs2(s);
                    fma2(acc[i][jj], wv, s);
                    fma2(acc[i][jj], wv, a);
                }
        }
        __syncthreads();
    }
    float bb = bq2[0];
    #pragma unroll
    for (int i = 0; i < 4; i++) {
        int u = u0 + ty + 16 * i;
        #pragma unroll
        for (int jj = 0; jj < 2; jj++) {
            int p = p0 + tx + 16 * jj;
            float lo, hi; unpack2(acc[i][jj], lo, hi);
            float z = lo + hi + bb;
            out[u * P_CNT + p] = 1.f / (1.f + __expf(-z));
        }
    }
}

// ---------------- driver --------------------------------------------------------
extern "C" void kernel_launch(void* const* d_in, const int* in_sizes, int n_in,
                              void* d_out, int out_size) {
    const int*   uid  = (const int*)  d_in[0];
    const int*   pid  = (const int*)  d_in[1];
    const int*   edge = (const int*)  d_in[2];
    // d_in[3] = user_paper_interactions (unused by the reference math)
    const float* ue   = (const float*)d_in[4];
    const float* pe   = (const float*)d_in[5];
    const float* W0   = (const float*)d_in[6];  const float* b0 = (const float*)d_in[7];
    const float* W1   = (const float*)d_in[8];  const float* b1 = (const float*)d_in[9];
    const float* W2   = (const float*)d_in[10]; const float* b2 = (const float*)d_in[11];
    const float* Wu   = (const float*)d_in[12]; const float* bu = (const float*)d_in[13];
    const float* Wp   = (const float*)d_in[14]; const float* bp = (const float*)d_in[15];
    const float* Wq1  = (const float*)d_in[16]; const float* bq1= (const float*)d_in[17];
    const float* Wq2  = (const float*)d_in[18]; const float* bq2= (const float*)d_in[19];
    float* out = (float*)d_out;

    float *xA, *xB, *h;
    cudaGetSymbolAddress((void**)&xA, g_xA);
    cudaGetSymbolAddress((void**)&xB, g_xB);
    cudaGetSymbolAddress((void**)&h,  g_h);

    // P1: x0 gather + degree count + fused projector weight products
    prep_kernel<<<834, 256>>>(uid, pid, ue, pe, edge, Wu, bu, Wp, bp, Wq1, bq1);
    // P2: degrees -> rsqrt + CSR row ptr
    scan_kernel<<<1, 32>>>();
    // P3: CSR fill (edges + self loops)
    fill_kernel<<<(E_CNT + N_NODES + 255) / 256, 256>>>(edge);

    // GCN layer 1 (aggregate-first): xA[.,128] -> agg -> @W0 -> relu -> xA[.,256]
    agg128_kernel<<<N_NODES, 256>>>(xA, xB);
    gemm_kernel<<<dim3(4, N_NODES / 32), 256>>>(xB, W0, b0, xA, D_DIM, 1);
    // GCN layer 2
    agg256_kernel<<<N_NODES, 256>>>(xA, h);
    gemm_kernel<<<dim3(4, N_NODES / 32), 256>>>(h, W1, b1, xB, H_DIM, 1);
    // GCN layer 3
    agg256_kernel<<<N_NODES, 256>>>(xB, h);
    gemm_kernel<<<dim3(4, N_NODES / 32), 256>>>(h, W2, b2, xA, H_DIM, 1);

    // fused projector: AB = xA @ (C1|C2) + bias  (Au rows 0..511, Bp rows 512..1535)
    gemm_ab_kernel<<<dim3(4, N_NODES / 32), 256>>>(xA);

    // pairwise sigmoid(relu(A[u]+B[p]) . w2 + bq2)
    pred_kernel<<<dim3(P_CNT / 32, U_CNT / 64), 256>>>(Wq2, bq2, out);
}